// round 3
// baseline (speedup 1.0000x reference)
#include <cuda_runtime.h>
#include <cstdint>

#define N_NODES 100000
#define N_EDGES 3200000

// Scratch (static device globals — no allocation allowed).
// .x = denom accumulator (later reciprocal), .y = numer accumulator.
// Interleaved so both per-edge atomics hit the same 32B L2 sector.
__device__ float2 g_acc[N_NODES];

__global__ void init_kernel() {
    int i = blockIdx.x * blockDim.x + threadIdx.x;
    if (i < N_NODES) {
        g_acc[i] = make_float2(0.0f, 0.0f);
    }
}

// Edge pass, 2 edges per thread (stride-by-blockDim for coalescing):
//  - pair_pred = leaky_relu([x_src, x_dst] @ Wn + ea @ We, 0.2)
//  - ex = exp(p0 - p1)   (softmax is shift-invariant; |score| << 88)
//  - write pair_pred, write ex into attn slot
//  - g_acc[dst] += (ex, ex * x[src])
__global__ void __launch_bounds__(256) edge_kernel(
                            const float* __restrict__ x,
                            const int*   __restrict__ ei,
                            const float* __restrict__ ea,
                            const float* __restrict__ Wn,
                            const float* __restrict__ We,
                            float* __restrict__ attn_ex,
                            float* __restrict__ pp_out)
{
    __shared__ float sWe[32];
    __shared__ float sWn[4];
    int t = threadIdx.x;
    if (t < 32)       sWe[t]      = We[t];
    else if (t < 36)  sWn[t - 32] = Wn[t - 32];
    __syncthreads();

    int base = blockIdx.x * (256 * 2) + t;
    int e0 = base;
    int e1 = base + 256;

    // Front-batch all global loads (indices, gathers, edge_attr) for MLP.
    int src0 = ei[e0],            src1 = ei[e1];
    int dst0 = ei[N_EDGES + e0],  dst1 = ei[N_EDGES + e1];

    float xs0 = __ldg(x + src0), xd0 = __ldg(x + dst0);
    float xs1 = __ldg(x + src1), xd1 = __ldg(x + dst1);

    const float4* ea40 = (const float4*)(ea + (size_t)e0 * 16);
    const float4* ea41 = (const float4*)(ea + (size_t)e1 * 16);
    float4 v0[4], v1[4];
#pragma unroll
    for (int i = 0; i < 4; i++) v0[i] = ea40[i];
#pragma unroll
    for (int i = 0; i < 4; i++) v1[i] = ea41[i];

    float p00 = xs0 * sWn[0] + xd0 * sWn[2];
    float p01 = xs0 * sWn[1] + xd0 * sWn[3];
    float p10 = xs1 * sWn[0] + xd1 * sWn[2];
    float p11 = xs1 * sWn[1] + xd1 * sWn[3];

#pragma unroll
    for (int i = 0; i < 4; i++) {
        p00 += v0[i].x * sWe[(i * 4 + 0) * 2] + v0[i].y * sWe[(i * 4 + 1) * 2]
             + v0[i].z * sWe[(i * 4 + 2) * 2] + v0[i].w * sWe[(i * 4 + 3) * 2];
        p01 += v0[i].x * sWe[(i * 4 + 0) * 2 + 1] + v0[i].y * sWe[(i * 4 + 1) * 2 + 1]
             + v0[i].z * sWe[(i * 4 + 2) * 2 + 1] + v0[i].w * sWe[(i * 4 + 3) * 2 + 1];
        p10 += v1[i].x * sWe[(i * 4 + 0) * 2] + v1[i].y * sWe[(i * 4 + 1) * 2]
             + v1[i].z * sWe[(i * 4 + 2) * 2] + v1[i].w * sWe[(i * 4 + 3) * 2];
        p11 += v1[i].x * sWe[(i * 4 + 0) * 2 + 1] + v1[i].y * sWe[(i * 4 + 1) * 2 + 1]
             + v1[i].z * sWe[(i * 4 + 2) * 2 + 1] + v1[i].w * sWe[(i * 4 + 3) * 2 + 1];
    }

    p00 = (p00 > 0.0f) ? p00 : 0.2f * p00;
    p01 = (p01 > 0.0f) ? p01 : 0.2f * p01;
    p10 = (p10 > 0.0f) ? p10 : 0.2f * p10;
    p11 = (p11 > 0.0f) ? p11 : 0.2f * p11;

    ((float2*)pp_out)[e0] = make_float2(p00, p01);
    ((float2*)pp_out)[e1] = make_float2(p10, p11);

    float ex0 = __expf(p00 - p01);
    float ex1 = __expf(p10 - p11);
    attn_ex[e0] = ex0;
    attn_ex[e1] = ex1;

    atomicAdd(&g_acc[dst0].x, ex0);
    atomicAdd(&g_acc[dst0].y, ex0 * xs0);
    atomicAdd(&g_acc[dst1].x, ex1);
    atomicAdd(&g_acc[dst1].y, ex1 * xs1);
}

// out[i] = W0 * numer * inv_denom ; stash inv_denom for the attn pass.
__global__ void node_kernel(float* __restrict__ out, const float* __restrict__ W) {
    int i = blockIdx.x * blockDim.x + threadIdx.x;
    if (i < N_NODES) {
        float2 a = g_acc[i];
        float inv = 1.0f / (a.x + 1e-16f);
        out[i] = W[0] * a.y * inv;
        g_acc[i].x = inv;   // reciprocal for the normalize pass
    }
}

// Normalize pass, 4 edges per thread, vector loads.
__global__ void __launch_bounds__(256) attn_kernel(
                            const int* __restrict__ ei,
                            float* __restrict__ attn)
{
    int e = (blockIdx.x * blockDim.x + threadIdx.x) * 4;
    if (e >= N_EDGES) return;

    int4   d  = *(const int4*)(ei + N_EDGES + e);
    float4 ex = *(const float4*)(attn + e);

    float i0 = g_acc[d.x].x;
    float i1 = g_acc[d.y].x;
    float i2 = g_acc[d.z].x;
    float i3 = g_acc[d.w].x;

    *(float4*)(attn + e) = make_float4(ex.x * i0, ex.y * i1, ex.z * i2, ex.w * i3);
}

extern "C" void kernel_launch(void* const* d_in, const int* in_sizes, int n_in,
                              void* d_out, int out_size)
{
    // Resolve inputs by element count (all distinct) — robust to ordering.
    const float* x  = nullptr;   // 100000
    const int*   ei = nullptr;   // 6400000 (int32)
    const float* ea = nullptr;   // 51200000
    const float* W  = nullptr;   // 1
    const float* Wn = nullptr;   // 4
    const float* We = nullptr;   // 32
    for (int i = 0; i < n_in; i++) {
        switch (in_sizes[i]) {
            case N_NODES:      x  = (const float*)d_in[i]; break;
            case 2 * N_EDGES:  ei = (const int*)d_in[i];   break;
            case 16 * N_EDGES: ea = (const float*)d_in[i]; break;
            case 1:            W  = (const float*)d_in[i]; break;
            case 4:            Wn = (const float*)d_in[i]; break;
            case 32:           We = (const float*)d_in[i]; break;
        }
    }

    float* out  = (float*)d_out;                 // [N]
    float* attn = out + N_NODES;                 // [E]
    float* pp   = out + N_NODES + N_EDGES;       // [E,2]

    init_kernel<<<(N_NODES + 255) / 256, 256>>>();
    edge_kernel<<<N_EDGES / (256 * 2), 256>>>(x, ei, ea, Wn, We, attn, pp);
    node_kernel<<<(N_NODES + 255) / 256, 256>>>(out, W);
    attn_kernel<<<N_EDGES / (256 * 4), 256>>>(ei, attn);
}

// round 5
// speedup vs baseline: 1.3263x; 1.3263x over previous
#include <cuda_runtime.h>
#include <cstdint>

#define N_NODES 100000
#define N_EDGES 3200000

// Scratch (static device globals — no allocation allowed).
// g_acc: .x = denom, .y = numer (single v2 reduction target per edge).
// g_inv: dense reciprocal array for the normalize pass (small gather footprint).
__device__ float2 g_acc[N_NODES];
__device__ float  g_inv[N_NODES];

__global__ void init_kernel() {
    int i = blockIdx.x * blockDim.x + threadIdx.x;
    if (i < N_NODES) {
        g_acc[i] = make_float2(0.0f, 0.0f);
    }
}

__device__ __forceinline__ void red_add_v2(float2* addr, float a, float b) {
    asm volatile("red.global.add.v2.f32 [%0], {%1, %2};"
                 :: "l"(addr), "f"(a), "f"(b) : "memory");
}

// Edge pass, 1 edge/thread:
//  - pair_pred = leaky_relu([x_src, x_dst] @ Wn + ea @ We, 0.2)
//  - ex = exp(p0 - p1)   (softmax is shift-invariant; |score| << 88)
//  - write pair_pred (streaming), write ex into attn slot (streaming)
//  - g_acc[dst] += (ex, ex * x[src])   via one red.v2
__global__ void __launch_bounds__(256) edge_kernel(
                            const float* __restrict__ x,
                            const int*   __restrict__ ei,
                            const float* __restrict__ ea,
                            const float* __restrict__ Wn,
                            const float* __restrict__ We,
                            float* __restrict__ attn_ex,
                            float* __restrict__ pp_out)
{
    __shared__ float sWe[32];
    __shared__ float sWn[4];
    int t = threadIdx.x;
    if (t < 32)       sWe[t]      = We[t];
    else if (t < 36)  sWn[t - 32] = Wn[t - 32];
    __syncthreads();

    int e = blockIdx.x * blockDim.x + t;
    if (e >= N_EDGES) return;

    int src = ei[e];
    int dst = ei[N_EDGES + e];
    float xs = __ldg(x + src);
    float xd = __ldg(x + dst);

    // edge_attr is a pure stream — evict-first so it doesn't pollute L2.
    const float4* ea4 = (const float4*)(ea + (size_t)e * 16);
    float4 v0 = __ldcs(ea4 + 0);
    float4 v1 = __ldcs(ea4 + 1);
    float4 v2 = __ldcs(ea4 + 2);
    float4 v3 = __ldcs(ea4 + 3);

    float p0 = xs * sWn[0] + xd * sWn[2];
    float p1 = xs * sWn[1] + xd * sWn[3];

    p0 += v0.x * sWe[0]  + v0.y * sWe[2]  + v0.z * sWe[4]  + v0.w * sWe[6];
    p1 += v0.x * sWe[1]  + v0.y * sWe[3]  + v0.z * sWe[5]  + v0.w * sWe[7];
    p0 += v1.x * sWe[8]  + v1.y * sWe[10] + v1.z * sWe[12] + v1.w * sWe[14];
    p1 += v1.x * sWe[9]  + v1.y * sWe[11] + v1.z * sWe[13] + v1.w * sWe[15];
    p0 += v2.x * sWe[16] + v2.y * sWe[18] + v2.z * sWe[20] + v2.w * sWe[22];
    p1 += v2.x * sWe[17] + v2.y * sWe[19] + v2.z * sWe[21] + v2.w * sWe[23];
    p0 += v3.x * sWe[24] + v3.y * sWe[26] + v3.z * sWe[28] + v3.w * sWe[30];
    p1 += v3.x * sWe[25] + v3.y * sWe[27] + v3.z * sWe[29] + v3.w * sWe[31];

    // leaky_relu(., 0.2)
    p0 = (p0 > 0.0f) ? p0 : 0.2f * p0;
    p1 = (p1 > 0.0f) ? p1 : 0.2f * p1;

    __stcs((float2*)pp_out + e, make_float2(p0, p1));

    float ex = __expf(p0 - p1);
    __stcs(attn_ex + e, ex);

    red_add_v2(&g_acc[dst], ex, ex * xs);
}

// out[i] = W0 * numer * inv_denom ; stash inv_denom densely for the attn pass.
__global__ void node_kernel(float* __restrict__ out, const float* __restrict__ W) {
    int i = blockIdx.x * blockDim.x + threadIdx.x;
    if (i < N_NODES) {
        float2 a = g_acc[i];
        float inv = 1.0f / (a.x + 1e-16f);
        out[i] = W[0] * a.y * inv;
        g_inv[i] = inv;
    }
}

// Normalize pass, 4 edges per thread, vector loads; gathers hit the dense
// 400KB g_inv array (L1-cacheable).
__global__ void __launch_bounds__(256) attn_kernel(
                            const int* __restrict__ ei,
                            float* __restrict__ attn)
{
    int e = (blockIdx.x * blockDim.x + threadIdx.x) * 4;
    if (e >= N_EDGES) return;

    int4   d  = __ldcs((const int4*)(ei + N_EDGES + e));
    float4 ex = __ldcs((const float4*)(attn + e));

    float i0 = __ldg(g_inv + d.x);
    float i1 = __ldg(g_inv + d.y);
    float i2 = __ldg(g_inv + d.z);
    float i3 = __ldg(g_inv + d.w);

    __stcs((float4*)(attn + e),
           make_float4(ex.x * i0, ex.y * i1, ex.z * i2, ex.w * i3));
}

extern "C" void kernel_launch(void* const* d_in, const int* in_sizes, int n_in,
                              void* d_out, int out_size)
{
    // Resolve inputs by element count (all distinct) — robust to ordering.
    const float* x  = nullptr;   // 100000
    const int*   ei = nullptr;   // 6400000 (int32)
    const float* ea = nullptr;   // 51200000
    const float* W  = nullptr;   // 1
    const float* Wn = nullptr;   // 4
    const float* We = nullptr;   // 32
    for (int i = 0; i < n_in; i++) {
        switch (in_sizes[i]) {
            case N_NODES:      x  = (const float*)d_in[i]; break;
            case 2 * N_EDGES:  ei = (const int*)d_in[i];   break;
            case 16 * N_EDGES: ea = (const float*)d_in[i]; break;
            case 1:            W  = (const float*)d_in[i]; break;
            case 4:            Wn = (const float*)d_in[i]; break;
            case 32:           We = (const float*)d_in[i]; break;
        }
    }

    float* out  = (float*)d_out;                 // [N]
    float* attn = out + N_NODES;                 // [E]
    float* pp   = out + N_NODES + N_EDGES;       // [E,2]

    init_kernel<<<(N_NODES + 255) / 256, 256>>>();
    edge_kernel<<<(N_EDGES + 255) / 256, 256>>>(x, ei, ea, Wn, We, attn, pp);
    node_kernel<<<(N_NODES + 255) / 256, 256>>>(out, W);
    attn_kernel<<<N_EDGES / (256 * 4), 256>>>(ei, attn);
}

// round 7
// speedup vs baseline: 1.3505x; 1.0183x over previous
#include <cuda_runtime.h>
#include <cstdint>

#define N_NODES 100000
#define N_EDGES 3200000

// Scratch (static device globals — no allocation allowed).
// g_acc: .x = denom, .y = numer (single v2 reduction target per edge).
// g_inv: dense reciprocal array for the normalize pass (small gather footprint).
__device__ float2 g_acc[N_NODES];
__device__ float  g_inv[N_NODES];

__global__ void init_kernel() {
    int i = blockIdx.x * blockDim.x + threadIdx.x;
    if (i < N_NODES) {
        g_acc[i] = make_float2(0.0f, 0.0f);
    }
}

__device__ __forceinline__ void red_add_v2(float2* addr, float a, float b) {
    asm volatile("red.global.add.v2.f32 [%0], {%1, %2};"
                 :: "l"(addr), "f"(a), "f"(b) : "memory");
}

// Edge pass, 1 edge/thread:
//  - pair_pred = leaky_relu([x_src, x_dst] @ Wn + ea @ We, 0.2)  -> written (default
//    policy: we WANT it L2-resident for the normalize pass to re-read)
//  - g_acc[dst] += (ex, ex * x[src])   via one red.v2
//  - ex itself is NOT stored; the normalize pass recomputes it from pair_pred.
__global__ void __launch_bounds__(256) edge_kernel(
                            const float* __restrict__ x,
                            const int*   __restrict__ ei,
                            const float* __restrict__ ea,
                            const float* __restrict__ Wn,
                            const float* __restrict__ We,
                            float* __restrict__ pp_out)
{
    __shared__ float sWe[32];
    __shared__ float sWn[4];
    int t = threadIdx.x;
    if (t < 32)       sWe[t]      = We[t];
    else if (t < 36)  sWn[t - 32] = Wn[t - 32];
    __syncthreads();

    int e = blockIdx.x * blockDim.x + t;
    if (e >= N_EDGES) return;

    int src = ei[e];
    int dst = ei[N_EDGES + e];
    float xs = __ldg(x + src);
    float xd = __ldg(x + dst);

    // edge_attr is a pure stream — evict-first so it doesn't pollute L2.
    const float4* ea4 = (const float4*)(ea + (size_t)e * 16);
    float4 v0 = __ldcs(ea4 + 0);
    float4 v1 = __ldcs(ea4 + 1);
    float4 v2 = __ldcs(ea4 + 2);
    float4 v3 = __ldcs(ea4 + 3);

    float p0 = xs * sWn[0] + xd * sWn[2];
    float p1 = xs * sWn[1] + xd * sWn[3];

    p0 += v0.x * sWe[0]  + v0.y * sWe[2]  + v0.z * sWe[4]  + v0.w * sWe[6];
    p1 += v0.x * sWe[1]  + v0.y * sWe[3]  + v0.z * sWe[5]  + v0.w * sWe[7];
    p0 += v1.x * sWe[8]  + v1.y * sWe[10] + v1.z * sWe[12] + v1.w * sWe[14];
    p1 += v1.x * sWe[9]  + v1.y * sWe[11] + v1.z * sWe[13] + v1.w * sWe[15];
    p0 += v2.x * sWe[16] + v2.y * sWe[18] + v2.z * sWe[20] + v2.w * sWe[22];
    p1 += v2.x * sWe[17] + v2.y * sWe[19] + v2.z * sWe[21] + v2.w * sWe[23];
    p0 += v3.x * sWe[24] + v3.y * sWe[26] + v3.z * sWe[28] + v3.w * sWe[30];
    p1 += v3.x * sWe[25] + v3.y * sWe[27] + v3.z * sWe[29] + v3.w * sWe[31];

    // leaky_relu(., 0.2)
    p0 = (p0 > 0.0f) ? p0 : 0.2f * p0;
    p1 = (p1 > 0.0f) ? p1 : 0.2f * p1;

    ((float2*)pp_out)[e] = make_float2(p0, p1);   // keep in L2 for attn pass

    float ex = __expf(p0 - p1);   // softmax is shift-invariant; |score| << 88
    red_add_v2(&g_acc[dst], ex, ex * xs);
}

// out[i] = W0 * numer * inv_denom ; stash inv_denom densely for the attn pass.
__global__ void node_kernel(float* __restrict__ out, const float* __restrict__ W) {
    int i = blockIdx.x * blockDim.x + threadIdx.x;
    if (i < N_NODES) {
        float2 a = g_acc[i];
        float inv = 1.0f / (a.x + 1e-16f);
        out[i] = W[0] * a.y * inv;
        g_inv[i] = inv;
    }
}

// Normalize pass, 4 edges/thread: re-read pair_pred (L2-hot), recompute ex,
// gather dense g_inv, write attn once (streaming).
__global__ void __launch_bounds__(256) attn_kernel(
                            const int*   __restrict__ ei,
                            const float* __restrict__ pp,
                            float* __restrict__ attn)
{
    int e = (blockIdx.x * blockDim.x + threadIdx.x) * 4;
    if (e >= N_EDGES) return;

    int4 d = *(const int4*)(ei + N_EDGES + e);

    // Issue the 4 random gathers early (longest latency).
    float i0 = __ldg(g_inv + d.x);
    float i1 = __ldg(g_inv + d.y);
    float i2 = __ldg(g_inv + d.z);
    float i3 = __ldg(g_inv + d.w);

    float4 pa = *(const float4*)(pp + 2 * (size_t)e);      // edges e, e+1
    float4 pb = *(const float4*)(pp + 2 * (size_t)e + 4);  // edges e+2, e+3

    float ex0 = __expf(pa.x - pa.y);
    float ex1 = __expf(pa.z - pa.w);
    float ex2 = __expf(pb.x - pb.y);
    float ex3 = __expf(pb.z - pb.w);

    __stcs((float4*)(attn + e),
           make_float4(ex0 * i0, ex1 * i1, ex2 * i2, ex3 * i3));
}

extern "C" void kernel_launch(void* const* d_in, const int* in_sizes, int n_in,
                              void* d_out, int out_size)
{
    // Resolve inputs by element count (all distinct) — robust to ordering.
    const float* x  = nullptr;   // 100000
    const int*   ei = nullptr;   // 6400000 (int32)
    const float* ea = nullptr;   // 51200000
    const float* W  = nullptr;   // 1
    const float* Wn = nullptr;   // 4
    const float* We = nullptr;   // 32
    for (int i = 0; i < n_in; i++) {
        switch (in_sizes[i]) {
            case N_NODES:      x  = (const float*)d_in[i]; break;
            case 2 * N_EDGES:  ei = (const int*)d_in[i];   break;
            case 16 * N_EDGES: ea = (const float*)d_in[i]; break;
            case 1:            W  = (const float*)d_in[i]; break;
            case 4:            Wn = (const float*)d_in[i]; break;
            case 32:           We = (const float*)d_in[i]; break;
        }
    }

    float* out  = (float*)d_out;                 // [N]
    float* attn = out + N_NODES;                 // [E]
    float* pp   = out + N_NODES + N_EDGES;       // [E,2]

    init_kernel<<<(N_NODES + 255) / 256, 256>>>();
    edge_kernel<<<(N_EDGES + 255) / 256, 256>>>(x, ei, ea, Wn, We, pp);
    node_kernel<<<(N_NODES + 255) / 256, 256>>>(out, W);
    attn_kernel<<<N_EDGES / (256 * 4), 256>>>(ei, pp, attn);
}